// round 17
// baseline (speedup 1.0000x reference)
#include <cuda_runtime.h>
#include <math.h>
#include <stdint.h>

#define NB 32
#define NG 16
#define NA 8400
#define NCLS 80
#define CAND 10
#define MAXFG (NB * NG * CAND)
#define LOSS_BLOCKS ((MAXFG * 32 + 255) / 256)

typedef unsigned long long u64;

// ---------------- scratch (device globals; zero-initialized at load,
// re-zeroed by kLoss's last block for the next invocation) -------------------
__device__ float2        g_ci  [(size_t)NB * NG * NA];   // (cost, iou), COMPACT i indexed
__device__ float         g_pbox[(size_t)NB * NA * 4];
__device__ int           g_ia  [(size_t)NB * NA];        // anchor -> compact index
__device__ int           g_best[(size_t)NB * NA];
__device__ int           g_cnt [(size_t)NB * NA];
__device__ int           g_gsum[(size_t)NB * NA];
__device__ int           g_ulist[(size_t)NB * NA];       // per-b packed: a | (interM<<16)
__device__ int           g_ucnt[NB];
__device__ int           g_list[MAXFG];
__device__ int           g_nfg;
__device__ int           g_done;
__device__ double        g_acc[4];   // loss_box, loss_conf, loss_cls, n_fg

static __device__ __forceinline__ void level_of(int a, int b,
                                                const float* p8, const float* p16, const float* p32,
                                                const float** P, int* HW, int* loc, float* s, int* w) {
    if (a < 6400)      { *P = p8  + (size_t)b * 85 * 6400; *HW = 6400; *loc = a;        *s = 8.f;  *w = 80; }
    else if (a < 8000) { *P = p16 + (size_t)b * 85 * 1600; *HW = 1600; *loc = a - 6400; *s = 16.f; *w = 40; }
    else               { *P = p32 + (size_t)b * 85 * 400;  *HW = 400;  *loc = a - 8000; *s = 32.f; *w = 20; }
}

static __device__ __forceinline__ void reduce1(float v, int slot) {
    int tid = threadIdx.x, lane = tid & 31, wid = tid >> 5;
    #pragma unroll
    for (int off = 16; off > 0; off >>= 1) v += __shfl_down_sync(0xffffffffu, v, off);
    __shared__ float sw[8];
    if (lane == 0) sw[wid] = v;
    __syncthreads();
    if (tid == 0) {
        float a0 = 0.f;
        #pragma unroll
        for (int i = 0; i < 8; i++) a0 += sw[i];
        atomicAdd(&g_acc[slot], (double)a0);
    }
}

static __device__ __forceinline__ void reduce4(float v0, float v1, float v2, float v3) {
    int tid = threadIdx.x, lane = tid & 31, wid = tid >> 5;
    #pragma unroll
    for (int off = 16; off > 0; off >>= 1) {
        v0 += __shfl_down_sync(0xffffffffu, v0, off);
        v1 += __shfl_down_sync(0xffffffffu, v1, off);
        v2 += __shfl_down_sync(0xffffffffu, v2, off);
        v3 += __shfl_down_sync(0xffffffffu, v3, off);
    }
    __shared__ float sw[8][4];
    if (lane == 0) { sw[wid][0] = v0; sw[wid][1] = v1; sw[wid][2] = v2; sw[wid][3] = v3; }
    __syncthreads();
    if (tid == 0) {
        float a0 = 0, a1 = 0, a2 = 0, a3 = 0;
        #pragma unroll
        for (int i = 0; i < 8; i++) { a0 += sw[i][0]; a1 += sw[i][1]; a2 += sw[i][2]; a3 += sw[i][3]; }
        if (a0 != 0.f) atomicAdd(&g_acc[0], (double)a0);
        if (a1 != 0.f) atomicAdd(&g_acc[1], (double)a1);
        if (a2 != 0.f) atomicAdd(&g_acc[2], (double)a2);
        if (a3 != 0.f) atomicAdd(&g_acc[3], (double)a3);
    }
}

// ---------------- kernel A1: geometry only (all anchors) ---------------------
__global__ void kA1(const float* __restrict__ p8, const float* __restrict__ p16,
                    const float* __restrict__ p32, const float* __restrict__ gtb) {
    int b   = blockIdx.y;
    int tid = threadIdx.x;
    int a   = blockIdx.x * blockDim.x + tid;

    __shared__ float sB[NG * 4];
    if (tid < NG * 4) sB[tid] = gtb[b * NG * 4 + tid];
    __syncthreads();

    float softp = 0.f;
    bool  uni = false;
    unsigned interM = 0;

    if (a < NA) {
        const float* P; int HW, loc, w; float s;
        level_of(a, b, p8, p16, p32, &P, &HW, &loc, &s, &w);
        P += loc;
        int ix = loc % w, iy = loc / w;
        float xc = ((float)ix + 0.5f) * s;
        float yc = ((float)iy + 0.5f) * s;
        float r2 = 2.5f * s;

        float cf = P[4 * HW];
        softp = fmaxf(cf, 0.f) + __logf(1.f + __expf(-fabsf(cf)));

        int idx = b * NA + a;
        g_cnt[idx] = 0;
        g_gsum[idx] = 0;

        #pragma unroll
        for (int g = 0; g < NG; g++) {
            float cx = sB[g * 4 + 0], cy = sB[g * 4 + 1];
            float gw = sB[g * 4 + 2], gh = sB[g * 4 + 3];
            float gminx = cx - gw * 0.5f, gmaxx = cx + gw * 0.5f;
            float gminy = cy - gh * 0.5f, gmaxy = cy + gh * 0.5f;
            bool inb = (xc - gminx > 0.f) && (gmaxx - xc > 0.f) &&
                       (yc - gminy > 0.f) && (gmaxy - yc > 0.f);
            bool inm = (xc - (cx - r2) > 0.f) && ((cx + r2) - xc > 0.f) &&
                       (yc - (cy - r2) > 0.f) && ((cy + r2) - yc > 0.f);
            if (inb && inm) interM |= (1u << g);
            uni = uni || inb || inm;
        }
    }

    unsigned mask = __ballot_sync(0xffffffffu, uni);
    if (uni) {
        int leader = __ffs(mask) - 1;
        int rank   = __popc(mask & ((1u << (tid & 31)) - 1u));
        int base = 0;
        if ((tid & 31) == leader) base = atomicAdd(&g_ucnt[b], __popc(mask));
        base = __shfl_sync(mask, base, leader);
        g_ulist[b * NA + base + rank] = a | ((int)interM << 16);
    }

    reduce1(softp, 1);
}

// ---------------- kernel A2: heavy math over compacted union list ------------
__global__ void kA2(const float* __restrict__ p8, const float* __restrict__ p16,
                    const float* __restrict__ p32, const float* __restrict__ gtb,
                    const int* __restrict__ gtc) {
    int b   = blockIdx.y;
    int tid = threadIdx.x;
    int i   = blockIdx.x * blockDim.x + tid;

    int n = g_ucnt[b];
    if (blockIdx.x * blockDim.x >= n) return;

    __shared__ float sB[NG * 4];
    __shared__ int   sC[NG];
    __shared__ int   sSlot[NCLS];
    __shared__ float sD[NG * 256];

    if (tid < NG * 4) sB[tid] = gtb[b * NG * 4 + tid];
    if (tid < NG)     sC[tid] = gtc[b * NG + tid];
    if (tid < NCLS)   sSlot[tid] = -1;
    __syncthreads();
    if (tid == 0) {
        #pragma unroll
        for (int g = 0; g < NG; g++)
            if (sSlot[sC[g]] < 0) sSlot[sC[g]] = g;
    }
    __syncthreads();

    if (i >= n) return;

    int packed = g_ulist[b * NA + i];
    int a      = packed & 0xffff;
    unsigned interM = (unsigned)packed >> 16;

    const float* P; int HW, loc, w; float s;
    level_of(a, b, p8, p16, p32, &P, &HW, &loc, &s, &w);
    P += loc;
    int ix = loc % w, iy = loc / w;
    int idx = b * NA + a;
    g_ia[idx] = i;

    float px = P[0], py = P[HW], pw = P[2 * HW], ph = P[3 * HW];
    float cf = P[4 * HW];
    float bx = (px + (float)ix) * s;
    float by = (py + (float)iy) * s;
    float bw = expf(pw) * s;
    float bh = expf(ph) * s;
    g_pbox[idx * 4 + 0] = bx; g_pbox[idx * 4 + 1] = by;
    g_pbox[idx * 4 + 2] = bw; g_pbox[idx * 4 + 3] = bh;

    float rr = rsqrtf(1.f + __expf(-cf));

    float s2 = 0.f;
    #pragma unroll 2
    for (int c8 = 0; c8 < NCLS; c8 += 8) {
        float prod = 1.f;
        #pragma unroll
        for (int j = 0; j < 8; j++) {
            int c = c8 + j;
            float x = P[(5 + c) * HW];
            float p = rr * rsqrtf(1.f + __expf(-x));
            float t = fmaxf(1.f - p, 1e-12f);
            prod *= t;
            int slot = sSlot[c];
            if (slot >= 0)
                sD[slot * 256 + tid] = __logf(fmaxf(p, 1e-12f)) - __logf(t);
        }
        s2 += __log2f(prod);
    }
    float suml1 = s2 * 0.69314718055994531f;

    float areab = bw * bh;
    float bhw = bw * 0.5f, bhh = bh * 0.5f;
    float bestc = 3.402823466e38f;
    int   bestg = 0;
    size_t base = ((size_t)b * NG) * NA + i;

    for (int g = 0; g < NG; g++) {
        float cx = sB[g * 4 + 0], cy = sB[g * 4 + 1];
        float gw = sB[g * 4 + 2], gh = sB[g * 4 + 3];
        int   slot = sSlot[sC[g]];
        float d  = sD[slot * 256 + tid];
        float cls_cost = -(d + suml1);

        float tlx = fmaxf(cx - gw * 0.5f, bx - bhw);
        float tly = fmaxf(cy - gh * 0.5f, by - bhh);
        float brx = fminf(cx + gw * 0.5f, bx + bhw);
        float bry = fminf(cy + gh * 0.5f, by + bhh);
        float iw = fmaxf(brx - tlx, 0.f), ih = fmaxf(bry - tly, 0.f);
        float inter = iw * ih;
        float iou = inter / (gw * gh + areab - inter + 1e-16f);

        float cost = cls_cost - 3.f * __logf(iou + 1e-8f) +
                     (((interM >> g) & 1u) ? 0.f : 100000.f);
        if (cost < bestc) { bestc = cost; bestg = g; }

        g_ci[base + (size_t)g * NA] = make_float2(cost, iou);
    }
    g_best[idx] = bestg;
}

// ---------------- kernel B: scan + parallel merge tree -----------------------
// Per-thread sorted top-10 lists -> 8 levels of pairwise sorted-list merges.
// Cost lists merge as u64 keys (ordered_float<<32 | anchor) on threads [0,nl);
// iou lists merge as raw f32 descending on threads [128,128+nl) concurrently.
__global__ void kB() {
    const int T = 256;
    const float CSENT = 3.402823466e38f;
    const float ISENT = -3.402823466e38f;
    int bg  = blockIdx.x;          // b*16 + g
    int b   = bg >> 4;
    int tid = threadIdx.x;
    size_t cbase = (size_t)bg * NA;   // compact-i indexed

    float cv[CAND], iv[CAND];
    unsigned short cix[CAND];
    #pragma unroll
    for (int k = 0; k < CAND; k++) { cv[k] = CSENT; iv[k] = ISENT; cix[k] = 0; }

    int n = g_ucnt[b];
    for (int i = tid; i < n; i += T) {
        int a = g_ulist[b * NA + i] & 0xffff;
        float2 ci = g_ci[cbase + i];   // coalesced
        // min-cost list: strict < keeps encounter order (= index asc) for ties
        if (ci.x < cv[CAND - 1]) {
            float v = ci.x; unsigned short id = (unsigned short)a;
            #pragma unroll
            for (int k = 0; k < CAND; k++)
                if (v < cv[k]) {
                    float tv = cv[k]; cv[k] = v; v = tv;
                    unsigned short ti = cix[k]; cix[k] = id; id = ti;
                }
        }
        // max-iou list (values only)
        if (ci.y > iv[CAND - 1]) {
            float v = ci.y;
            #pragma unroll
            for (int k = 0; k < CAND; k++)
                if (v > iv[k]) { float tv = iv[k]; iv[k] = v; v = tv; }
        }
    }

    // ping-pong merge buffers
    __shared__ u64   bufA[T * CAND];          // 20 KB
    __shared__ u64   bufB[(T / 2) * CAND];    // 10 KB
    __shared__ float fA  [T * CAND];          // 10 KB
    __shared__ float fB  [(T / 2) * CAND];    //  5 KB

    // write per-thread sorted lists (ascending cost-key / descending iou)
    #pragma unroll
    for (int k = 0; k < CAND; k++) {
        unsigned cb = __float_as_uint(cv[k]);
        cb = (cb & 0x80000000u) ? ~cb : (cb | 0x80000000u);
        bufA[tid * CAND + k] = (((u64)cb) << 32) | (u64)cix[k];
        fA[tid * CAND + k]   = iv[k];
    }

    u64   *sC = bufA, *dC = bufB;
    float *sI = fA,   *dI = fB;

    #pragma unroll 1
    for (int nl = T / 2; nl >= 1; nl >>= 1) {
        __syncthreads();
        if (tid < nl) {
            const u64* A = sC + (2 * tid) * CAND;
            const u64* B = sC + (2 * tid + 1) * CAND;
            u64* O = dC + tid * CAND;
            int i = 0, j = 0;
            u64 av = A[0], bv = B[0];
            #pragma unroll
            for (int k = 0; k < CAND; k++) {
                if (av <= bv) { O[k] = av; ++i; av = (i < CAND) ? A[i] : ~0ull; }
                else          { O[k] = bv; ++j; bv = (j < CAND) ? B[j] : ~0ull; }
            }
        } else if (tid >= 128 && tid - 128 < nl) {
            int t = tid - 128;
            const float* A = sI + (2 * t) * CAND;
            const float* B = sI + (2 * t + 1) * CAND;
            float* O = dI + t * CAND;
            int i = 0, j = 0;
            float av = A[0], bv = B[0];
            #pragma unroll
            for (int k = 0; k < CAND; k++) {
                if (av >= bv) { O[k] = av; ++i; av = (i < CAND) ? A[i] : ISENT; }
                else          { O[k] = bv; ++j; bv = (j < CAND) ? B[j] : ISENT; }
            }
        }
        { u64* t0 = sC; sC = dC; dC = t0; }
        { float* t1 = sI; sI = dI; dI = t1; }
    }
    __syncthreads();

    // final lists: sC[0..9] (cost keys asc), sI[0..9] (iou desc)
    if (tid == 0) {
        float isum = 0.f;
        #pragma unroll
        for (int k = 0; k < CAND; k++) isum += sI[k];   // descending order sum
        int dynk = (int)isum;          // trunc, matches astype(int32)
        if (dynk < 1) dynk = 1;
        int g = bg & 15;
        #pragma unroll
        for (int k = 0; k < CAND; k++) {
            if (k < dynk) {
                int a   = (int)(sC[k] & 0xffffffffull);
                int idx = b * NA + a;
                int old = atomicAdd(&g_cnt[idx], 1);
                atomicAdd(&g_gsum[idx], g);
                if (old == 0) {
                    int pos = atomicAdd(&g_nfg, 1);
                    g_list[pos] = idx;
                }
            }
        }
    }
}

// ---------------- fg-only losses + fused final combine + state reset ---------
__global__ void kLoss(const float* __restrict__ p8, const float* __restrict__ p16,
                      const float* __restrict__ p32, const float* __restrict__ gtb,
                      const int* __restrict__ gtc, float* out) {
    int gid  = blockIdx.x * blockDim.x + threadIdx.x;
    int wi   = gid >> 5;
    int lane = gid & 31;

    float lb = 0.f, lcf = 0.f, lcl = 0.f, nf = 0.f;
    if (wi < g_nfg) {
        int idx = g_list[wi];
        int b = idx / NA, a = idx - b * NA;
        int cnt = g_cnt[idx];
        int gi = (cnt == 1) ? g_gsum[idx] : g_best[idx];
        int ii = g_ia[idx];
        float miou = g_ci[((size_t)(b * NG + gi)) * NA + ii].y;
        int tc = gtc[b * NG + gi];
        const float* P; int HW, loc, w; float s;
        level_of(a, b, p8, p16, p32, &P, &HW, &loc, &s, &w);
        P += loc;

        {
            int c0 = lane, c1 = lane + 32;
            float x0 = P[(5 + c0) * HW];
            float x1 = P[(5 + c1) * HW];
            float t0 = (c0 == tc) ? miou : 0.f;
            float t1 = (c1 == tc) ? miou : 0.f;
            lcl  = fmaxf(x0, 0.f) - x0 * t0 + __logf(1.f + __expf(-fabsf(x0)));
            lcl += fmaxf(x1, 0.f) - x1 * t1 + __logf(1.f + __expf(-fabsf(x1)));
            if (lane < 16) {
                int c2 = lane + 64;
                float x2 = P[(5 + c2) * HW];
                float t2 = (c2 == tc) ? miou : 0.f;
                lcl += fmaxf(x2, 0.f) - x2 * t2 + __logf(1.f + __expf(-fabsf(x2)));
            }
        }

        if (lane == 0) {
            float bx = g_pbox[idx * 4 + 0], by = g_pbox[idx * 4 + 1];
            float bw = g_pbox[idx * 4 + 2], bh = g_pbox[idx * 4 + 3];
            const float* gb = gtb + (b * NG + gi) * 4;
            float cx = gb[0], cy = gb[1], gw = gb[2], gh = gb[3];
            float tlx = fmaxf(bx - bw * 0.5f, cx - gw * 0.5f);
            float tly = fmaxf(by - bh * 0.5f, cy - gh * 0.5f);
            float brx = fminf(bx + bw * 0.5f, cx + gw * 0.5f);
            float bry = fminf(by + bh * 0.5f, cy + gh * 0.5f);
            float iw = fmaxf(brx - tlx, 0.f), ih = fmaxf(bry - tly, 0.f);
            float inter = iw * ih;
            float ioue = inter / (bw * bh + gw * gh - inter + 1e-16f);
            lb = 1.f - ioue * ioue;
            nf = 1.f;
            lcf = -P[4 * HW];
        }
    }
    reduce4(lb, lcf, lcl, nf);

    if (threadIdx.x == 0) {
        __threadfence();
        int t = atomicAdd(&g_done, 1);
        if (t == (int)gridDim.x - 1) {
            double nfg = g_acc[3];
            if (nfg < 1.0) nfg = 1.0;
            out[0] = (float)((5.0 * g_acc[0] + g_acc[1] + g_acc[2]) / nfg);
            g_acc[0] = 0.0; g_acc[1] = 0.0; g_acc[2] = 0.0; g_acc[3] = 0.0;
            g_nfg = 0;
            g_done = 0;
            #pragma unroll
            for (int i = 0; i < NB; i++) g_ucnt[i] = 0;
        }
    }
}

// ---------------- launcher -----------------------------------------------------
extern "C" void kernel_launch(void* const* d_in, const int* in_sizes, int n_in,
                              void* d_out, int out_size) {
    const float* p8  = (const float*)d_in[0];
    const float* p16 = (const float*)d_in[1];
    const float* p32 = (const float*)d_in[2];
    const float* gtb = (const float*)d_in[3];
    const int*   gtc = (const int*)d_in[4];
    (void)in_sizes; (void)n_in; (void)out_size;

    dim3 grid((NA + 255) / 256, NB);
    kA1<<<grid, 256>>>(p8, p16, p32, gtb);
    kA2<<<grid, 256>>>(p8, p16, p32, gtb, gtc);
    kB<<<NB * NG, 256>>>();
    kLoss<<<LOSS_BLOCKS, 256>>>(p8, p16, p32, gtb, gtc, (float*)d_out);
}